// round 12
// baseline (speedup 1.0000x reference)
#include <cuda_runtime.h>
#include <cstdint>

// ---------------------------------------------------------------------------
// GenAttentionMask (float32 output: 1.0f / 0.0f):
//   for b in range(batch):
//     s = seq_lengths[b]
//     out += head_num copies of (fp16(mask[b,0,:s,:s]) > 0.5) as float32
//
// fp16_rn(x) > 0.5  <=>  x > 0.500244140625f   (fp16 midpoint, ties-to-even)
//
// DRAM row-locality experiment: each block owns one (4096-elem chunk, head):
// 256 threads x 4 lane-adjacent float4s = 16KB contiguous write burst per
// block-head. Head is the fastest block dim so the 8 sibling blocks re-read
// the same input chunk from L2. One write stream per warp.
// ---------------------------------------------------------------------------

#define THRESH 0.500244140625f
#define CHUNK 4096                 // elements per (block, head)

__device__ __forceinline__ float4 thresh4(float4 f) {
    float4 v;
    v.x = (f.x > THRESH) ? 1.0f : 0.0f;
    v.y = (f.y > THRESH) ? 1.0f : 0.0f;
    v.z = (f.z > THRESH) ? 1.0f : 0.0f;
    v.w = (f.w > THRESH) ? 1.0f : 0.0f;
    return v;
}

// blockIdx.x = chunk*8 + head_lane ; blockIdx.y = batch.
__global__ void __launch_bounds__(256)
genmask_kernel(const float* __restrict__ in, float* __restrict__ out,
               const int* __restrict__ sl, const int* __restrict__ hn_ptr,
               int max_seq) {
    const int b = blockIdx.y;

    // Inline metadata: s = sl[b]; obase = hn * sum_{i<b} sl[i]^2.
    int hn = hn_ptr ? __ldg(hn_ptr) : 8;
    if (hn <= 0 || hn > 64) hn = 8;
    long long acc = 0;
#pragma unroll 1
    for (int i = 0; i < b; ++i) {
        int si = __ldg(sl + i);
        acc += (long long)si * si;
    }
    const unsigned s = (unsigned)__ldg(sl + b);
    const long long obase = acc * hn;
    const unsigned ssq = s * s;

    const unsigned bx    = blockIdx.x;
    const unsigned chunk = bx >> 3;
    const int      hl    = bx & 7;

    const unsigned base = chunk * CHUNK + threadIdx.x * 4;
    if (base >= ssq || hl >= hn) return;

    // 4 segments of 1024 elements; lane-adjacent float4 within each segment.
    // s is a multiple of 256, so a float4 never straddles an input row.
    float4 v[4];
    const float* ibatch = in + (size_t)b * max_seq * max_seq;
#pragma unroll
    for (int i = 0; i < 4; ++i) {
        unsigned p = base + (unsigned)i * 1024u;          // flat offset in s*s
        unsigned row = p / s;
        unsigned col = p - row * s;
        float4 f = *reinterpret_cast<const float4*>(ibatch + (size_t)row * max_seq + col);
        v[i] = thresh4(f);
    }

    float* ob = out + (size_t)obase + (size_t)hl * ssq + base;
#pragma unroll
    for (int i = 0; i < 4; ++i)
        __stcs(reinterpret_cast<float4*>(ob + (size_t)i * 1024u), v[i]);

    // Extra heads beyond 8 (generic hn), strided by 8 like the block fold.
    for (int h = hl + 8; h < hn; h += 8) {
        float* ob2 = out + (size_t)obase + (size_t)h * ssq + base;
#pragma unroll
        for (int i = 0; i < 4; ++i)
            __stcs(reinterpret_cast<float4*>(ob2 + (size_t)i * 1024u), v[i]);
    }
}

extern "C" void kernel_launch(void* const* d_in, const int* in_sizes, int n_in,
                              void* d_out, int out_size) {
    // Identify inputs by size, not position:
    //   mask        = largest input
    //   head_num    = 1-element input
    //   seq_lengths = the remaining one (batch = its element count)
    int mask_i = 0;
    for (int i = 1; i < n_in; ++i)
        if (in_sizes[i] > in_sizes[mask_i]) mask_i = i;
    int hn_i = -1, sl_i = -1;
    for (int i = 0; i < n_in; ++i) {
        if (i == mask_i) continue;
        if (in_sizes[i] == 1 && hn_i < 0) hn_i = i;
        else sl_i = i;
    }

    const float* mask = (const float*)d_in[mask_i];
    const int*   sl   = (const int*)d_in[sl_i];
    const int*   hn   = (hn_i >= 0) ? (const int*)d_in[hn_i] : nullptr;
    float* out = (float*)d_out;

    const int batch = in_sizes[sl_i];
    const long long msq = (long long)in_sizes[mask_i] / batch;   // max_seq^2

    // max_seq is a power of two (2048 here); recover it robustly
    int max_seq = 1;
    while ((long long)max_seq * max_seq < msq) max_seq <<= 1;

    const long long chunks = ((long long)max_seq * max_seq + CHUNK - 1) / CHUNK;
    dim3 block(256);
    dim3 grid((unsigned)(chunks * 8), batch);
    genmask_kernel<<<grid, block>>>(mask, out, sl, hn, max_seq);
}

// round 13
// speedup vs baseline: 1.2692x; 1.2692x over previous
#include <cuda_runtime.h>
#include <cstdint>

// ---------------------------------------------------------------------------
// GenAttentionMask (float32 output: 1.0f / 0.0f):
//   for b in range(batch):
//     s = seq_lengths[b]
//     out += head_num copies of (fp16(mask[b,0,:s,:s]) > 0.5) as float32
//
// fp16_rn(x) > 0.5  <=>  x > 0.500244140625f   (fp16 midpoint, ties-to-even)
//
// Converged configuration (best measured: 74.5us kernel, 71.5% DRAM —
// empirical mixed-stream HBM ceiling on GB300 for this 1:8 read:write
// pattern): adjacent lanes own adjacent float4s (fully-coalesced 128B lines);
// each thread handles two float4s half a row apart (MLP=2); 16 .cs stores
// (write-once stream, evict-first); metadata inline (single graph node).
// ---------------------------------------------------------------------------

#define THRESH 0.500244140625f

__device__ __forceinline__ float4 thresh4(float4 f) {
    float4 v;
    v.x = (f.x > THRESH) ? 1.0f : 0.0f;
    v.y = (f.y > THRESH) ? 1.0f : 0.0f;
    v.z = (f.z > THRESH) ? 1.0f : 0.0f;
    v.w = (f.w > THRESH) ? 1.0f : 0.0f;
    return v;
}

// One thread: two float4s of one row (cols col and col + s/2), written to all
// head replicas. shift indexes float4-groups per HALF row.
__global__ void __launch_bounds__(512)
genmask_kernel(const float* __restrict__ in, float* __restrict__ out,
               const int* __restrict__ sl, const int* __restrict__ hn_ptr,
               int max_seq, int shift) {
    const int b = blockIdx.y;

    // Inline metadata: s = sl[b]; obase = hn * sum_{i<b} sl[i]^2.
    // <=8 uniform __ldg's, warp-broadcast; amortized over 256B of stores.
    int hn = hn_ptr ? __ldg(hn_ptr) : 8;
    if (hn <= 0 || hn > 64) hn = 8;
    long long acc = 0;
#pragma unroll 1
    for (int i = 0; i < b; ++i) {
        int si = __ldg(sl + i);
        acc += (long long)si * si;
    }
    const int s = __ldg(sl + b);
    const long long obase = acc * hn;

    const int gid = blockIdx.x * blockDim.x + threadIdx.x;
    const int row  = gid >> shift;
    const int col  = (gid & ((1 << shift) - 1)) << 2;   // within first half-row
    const int half = s >> 1;
    if (row >= s || col >= half) return;

    const float* ib = in + (size_t)b * max_seq * max_seq + (size_t)row * max_seq;
    float4 f0 = *reinterpret_cast<const float4*>(ib + col);
    float4 f1 = *reinterpret_cast<const float4*>(ib + half + col);

    float4 v0 = thresh4(f0);
    float4 v1 = thresh4(f1);

    const size_t ss = (size_t)s * (size_t)s;  // head stride (elements)
    float* op = out + (size_t)obase + (size_t)row * s + col;

#pragma unroll 8
    for (int h = 0; h < hn; ++h) {
        __stcs(reinterpret_cast<float4*>(op), v0);
        __stcs(reinterpret_cast<float4*>(op + half), v1);
        op += ss;
    }
}

extern "C" void kernel_launch(void* const* d_in, const int* in_sizes, int n_in,
                              void* d_out, int out_size) {
    // Identify inputs by size, not position:
    //   mask        = largest input
    //   head_num    = 1-element input
    //   seq_lengths = the remaining one (batch = its element count)
    int mask_i = 0;
    for (int i = 1; i < n_in; ++i)
        if (in_sizes[i] > in_sizes[mask_i]) mask_i = i;
    int hn_i = -1, sl_i = -1;
    for (int i = 0; i < n_in; ++i) {
        if (i == mask_i) continue;
        if (in_sizes[i] == 1 && hn_i < 0) hn_i = i;
        else sl_i = i;
    }

    const float* mask = (const float*)d_in[mask_i];
    const int*   sl   = (const int*)d_in[sl_i];
    const int*   hn   = (hn_i >= 0) ? (const int*)d_in[hn_i] : nullptr;
    float* out = (float*)d_out;

    const int batch = in_sizes[sl_i];
    const long long msq = (long long)in_sizes[mask_i] / batch;   // max_seq^2

    // max_seq is a power of two (2048 here); recover it robustly
    int max_seq = 1;
    while ((long long)max_seq * max_seq < msq) max_seq <<= 1;

    // float4-groups per HALF row, padded to a power of two
    const int gpr_pad = max_seq / 8;
    int shift = 0;
    while ((1 << shift) < gpr_pad) ++shift;

    const long long threads_per_batch = (long long)max_seq * gpr_pad;
    dim3 block(512);
    dim3 grid((unsigned)((threads_per_batch + 511) / 512), batch);
    genmask_kernel<<<grid, block>>>(mask, out, sl, hn, max_seq, shift);
}